// round 1
// baseline (speedup 1.0000x reference)
#include <cuda_runtime.h>
#include <cstdint>

#define BATCH   32768
#define KNB     16

// ---------------- device scratch (static, allocation-free) ----------------
__device__ float g_W1[768 * 256];                 // rows 0-255: M^T, 256-511: Wg, 512-767: Wo1
__device__ float g_W2[256 * 256];                 // Wo2 (cols 256..511 of Wo)
__device__ float g_E[(size_t)BATCH * 768];        // per-row: P[0:256) | gate[256:512) | E1[512:768)
__device__ float g_ctx[(size_t)BATCH * 256];      // gated context

__device__ __forceinline__ uint32_t f2tf32(float x) {
    uint32_t y;
    asm("cvt.rna.tf32.f32 %0, %1;" : "=r"(y) : "f"(x));
    return y;
}

__device__ __forceinline__ float warp_sum(float v) {
    v += __shfl_xor_sync(0xffffffffu, v, 16);
    v += __shfl_xor_sync(0xffffffffu, v, 8);
    v += __shfl_xor_sync(0xffffffffu, v, 4);
    v += __shfl_xor_sync(0xffffffffu, v, 2);
    v += __shfl_xor_sync(0xffffffffu, v, 1);
    return v;
}

// ---------------- K0: build fused weight matrices -------------------------
// M[d][e] = sum_a Wq[a][d] * Wk[a][e];  W1 row j (j<256) is M^T row j:
// W1[j][e] = sum_a Wq[a][e] * Wk[a][j]   (so P[b][j] = center[b] . W1[j])
__global__ void prep_kernel(const float* __restrict__ Wq, const float* __restrict__ Wk,
                            const float* __restrict__ Wg, const float* __restrict__ Wo) {
    int j = blockIdx.x;
    int e = threadIdx.x;
    if (j < 256) {
        float s = 0.f;
#pragma unroll 8
        for (int a = 0; a < 64; a++)
            s = fmaf(Wq[a * 256 + e], Wk[a * 256 + j], s);
        g_W1[j * 256 + e] = s;
    } else if (j < 512) {
        g_W1[j * 256 + e] = Wg[(j - 256) * 256 + e];
    } else if (j < 768) {
        g_W1[j * 256 + e] = Wo[(j - 512) * 512 + e];
    } else {
        g_W2[(j - 768) * 256 + e] = Wo[(j - 768) * 512 + 256 + e];
    }
}

// ---------------- GEMM (tf32 mma.sync m16n8k8), 128x128 tile, BK=32 -------
// EPI==0: A = gathered centers, B = g_W1 (N=768), epilogue writes P/gate/E1 into g_E
// EPI==1: A = g_ctx,            B = g_W2 (N=256), epilogue out = acc + E1 + center
template <int EPI>
__global__ __launch_bounds__(256, 2)
void gemm_kernel(const float* __restrict__ all_embs,
                 const int* __restrict__ center_idx,
                 const float* __restrict__ bg,
                 const float* __restrict__ bo,
                 float* __restrict__ out) {
    __shared__ float As[32][132];   // [k][m], pad 132 -> conflict-free frag loads
    __shared__ float Bs[32][132];   // [k][n]
    __shared__ int   ridx[128];

    const int t    = threadIdx.x;
    const int lane = t & 31;
    const int warp = t >> 5;
    const int m0 = blockIdx.x * 128;
    const int n0 = blockIdx.y * 128;
    const float* Bmat = (EPI == 0) ? g_W1 : g_W2;

    if (t < 128) ridx[t] = center_idx[m0 + t];
    __syncthreads();

    float acc[2][8][4] = {};

    const int g  = lane >> 2;
    const int tg = lane & 3;
    const int mb  = (warp & 3) * 32;   // 4 warps along M
    const int nbo = (warp >> 2) * 64;  // 2 warps along N

    for (int kk = 0; kk < 256; kk += 32) {
        // load A tile (transpose into [k][m]); warp w handles k-cols 4w..4w+3
#pragma unroll
        for (int p = 0; p < 4; p++) {
            int mr = p * 32 + lane;
            const float* arow = (EPI == 0)
                ? (all_embs + (size_t)ridx[mr] * 256)
                : (g_ctx + (size_t)(m0 + mr) * 256);
            float4 v = *(const float4*)(arow + kk + warp * 4);
            As[warp * 4 + 0][mr] = __uint_as_float(f2tf32(v.x));
            As[warp * 4 + 1][mr] = __uint_as_float(f2tf32(v.y));
            As[warp * 4 + 2][mr] = __uint_as_float(f2tf32(v.z));
            As[warp * 4 + 3][mr] = __uint_as_float(f2tf32(v.w));
        }
        // load B tile ([k][n])
#pragma unroll
        for (int p = 0; p < 4; p++) {
            int nr = p * 32 + lane;
            const float* brow = Bmat + (size_t)(n0 + nr) * 256;
            float4 v = *(const float4*)(brow + kk + warp * 4);
            Bs[warp * 4 + 0][nr] = __uint_as_float(f2tf32(v.x));
            Bs[warp * 4 + 1][nr] = __uint_as_float(f2tf32(v.y));
            Bs[warp * 4 + 2][nr] = __uint_as_float(f2tf32(v.z));
            Bs[warp * 4 + 3][nr] = __uint_as_float(f2tf32(v.w));
        }
        __syncthreads();

#pragma unroll
        for (int ks = 0; ks < 4; ks++) {
            const int k0 = ks * 8;
            uint32_t a[2][4];
#pragma unroll
            for (int mt = 0; mt < 2; mt++) {
                int m = mb + mt * 16 + g;
                a[mt][0] = __float_as_uint(As[k0 + tg][m]);
                a[mt][1] = __float_as_uint(As[k0 + tg][m + 8]);
                a[mt][2] = __float_as_uint(As[k0 + tg + 4][m]);
                a[mt][3] = __float_as_uint(As[k0 + tg + 4][m + 8]);
            }
            uint32_t bf[8][2];
#pragma unroll
            for (int nt = 0; nt < 8; nt++) {
                int n = nbo + nt * 8 + g;
                bf[nt][0] = __float_as_uint(Bs[k0 + tg][n]);
                bf[nt][1] = __float_as_uint(Bs[k0 + tg + 4][n]);
            }
#pragma unroll
            for (int mt = 0; mt < 2; mt++)
#pragma unroll
                for (int nt = 0; nt < 8; nt++)
                    asm volatile(
                        "mma.sync.aligned.m16n8k8.row.col.f32.tf32.tf32.f32 "
                        "{%0,%1,%2,%3}, {%4,%5,%6,%7}, {%8,%9}, {%0,%1,%2,%3};\n"
                        : "+f"(acc[mt][nt][0]), "+f"(acc[mt][nt][1]),
                          "+f"(acc[mt][nt][2]), "+f"(acc[mt][nt][3])
                        : "r"(a[mt][0]), "r"(a[mt][1]), "r"(a[mt][2]), "r"(a[mt][3]),
                          "r"(bf[nt][0]), "r"(bf[nt][1]));
        }
        __syncthreads();
    }

    // epilogue: c0 (row g, col 2tg), c1 (+1), c2 (row g+8), c3 (row g+8, +1)
#pragma unroll
    for (int mt = 0; mt < 2; mt++) {
#pragma unroll
        for (int nt = 0; nt < 8; nt++) {
            int lc = nbo + nt * 8 + tg * 2;
#pragma unroll
            for (int h = 0; h < 2; h++) {
                int lr  = mb + mt * 16 + g + h * 8;
                int row = m0 + lr;
                float v0 = acc[mt][nt][h * 2 + 0];
                float v1 = acc[mt][nt][h * 2 + 1];
                int j = n0 + lc;
                if (EPI == 0) {
                    if (j < 256) {
                        // P: raw
                    } else if (j < 512) {
                        v0 = 1.f / (1.f + __expf(-(v0 + bg[j - 256])));
                        v1 = 1.f / (1.f + __expf(-(v1 + bg[j - 255])));
                    } else {
                        v0 += bo[j - 512];
                        v1 += bo[j - 511];
                    }
                    *(float2*)(g_E + (size_t)row * 768 + j) = make_float2(v0, v1);
                } else {
                    float2 e1 = *(const float2*)(g_E + (size_t)row * 768 + 512 + j);
                    const float* cen = all_embs + (size_t)ridx[lr] * 256;
                    float2 c2 = *(const float2*)(cen + j);
                    v0 += e1.x + c2.x;
                    v1 += e1.y + c2.y;
                    *(float2*)(out + (size_t)row * 256 + j) = make_float2(v0, v1);
                }
            }
        }
    }
}

// ---------------- K2: neighbor gather + logits + softmax + gated context --
// One warp per batch row. 16 neighbor rows cached in registers (read ONCE).
__global__ __launch_bounds__(256, 1)
void neigh_kernel(const float* __restrict__ all_embs,
                  const int* __restrict__ nb_idx,
                  const float* __restrict__ nb_w) {
    const int warp = threadIdx.x >> 5;
    const int lane = threadIdx.x & 31;
    const int b = blockIdx.x * 8 + warp;

    int   myidx = 0;
    float mylw  = 0.f;
    if (lane < 16) {
        myidx = nb_idx[b * 16 + lane];
        mylw  = __logf(fmaxf(nb_w[b * 16 + lane], 1e-6f));
    }

    float4 nlo[16], nhi[16];
#pragma unroll
    for (int k = 0; k < 16; k++) {
        int r = __shfl_sync(0xffffffffu, myidx, k);
        const float4* rp = (const float4*)(all_embs + (size_t)r * 256);
        nlo[k] = rp[lane];
        nhi[k] = rp[32 + lane];
    }

    const float4* prow = (const float4*)(g_E + (size_t)b * 768);
    float4 plo = prow[lane], phi = prow[32 + lane];

    float logit[16];
#pragma unroll
    for (int k = 0; k < 16; k++) {
        float s = nlo[k].x * plo.x + nlo[k].y * plo.y + nlo[k].z * plo.z + nlo[k].w * plo.w
                + nhi[k].x * phi.x + nhi[k].y * phi.y + nhi[k].z * phi.z + nhi[k].w * phi.w;
        s = warp_sum(s);
        float lw = __shfl_sync(0xffffffffu, mylw, k);
        logit[k] = s * 0.125f + lw;   // SCALE = 64^-0.5
    }

    float mx = logit[0];
#pragma unroll
    for (int k = 1; k < 16; k++) mx = fmaxf(mx, logit[k]);
    float esum = 0.f;
#pragma unroll
    for (int k = 0; k < 16; k++) { logit[k] = __expf(logit[k] - mx); esum += logit[k]; }
    float inv = 1.f / esum;

    float4 clo = make_float4(0, 0, 0, 0), chi = make_float4(0, 0, 0, 0);
#pragma unroll
    for (int k = 0; k < 16; k++) {
        float a = logit[k] * inv;
        clo.x = fmaf(a, nlo[k].x, clo.x); clo.y = fmaf(a, nlo[k].y, clo.y);
        clo.z = fmaf(a, nlo[k].z, clo.z); clo.w = fmaf(a, nlo[k].w, clo.w);
        chi.x = fmaf(a, nhi[k].x, chi.x); chi.y = fmaf(a, nhi[k].y, chi.y);
        chi.z = fmaf(a, nhi[k].z, chi.z); chi.w = fmaf(a, nhi[k].w, chi.w);
    }

    const float4* grow = (const float4*)(g_E + (size_t)b * 768 + 256);
    float4 glo = grow[lane], ghi = grow[32 + lane];
    float4* crow = (float4*)(g_ctx + (size_t)b * 256);
    crow[lane]      = make_float4(glo.x * clo.x, glo.y * clo.y, glo.z * clo.z, glo.w * clo.w);
    crow[32 + lane] = make_float4(ghi.x * chi.x, ghi.y * chi.y, ghi.z * chi.z, ghi.w * chi.w);
}

// ---------------- K4: layernorm (in-place on d_out) ------------------------
__global__ void ln_kernel(float* __restrict__ out,
                          const float* __restrict__ gamma,
                          const float* __restrict__ beta) {
    const int warp = threadIdx.x >> 5;
    const int lane = threadIdx.x & 31;
    const int r = blockIdx.x * 8 + warp;
    float4* row = (float4*)(out + (size_t)r * 256);
    float4 x0 = row[lane], x1 = row[32 + lane];

    float s  = x0.x + x0.y + x0.z + x0.w + x1.x + x1.y + x1.z + x1.w;
    float sq = x0.x * x0.x + x0.y * x0.y + x0.z * x0.z + x0.w * x0.w
             + x1.x * x1.x + x1.y * x1.y + x1.z * x1.z + x1.w * x1.w;
    s  = warp_sum(s);
    sq = warp_sum(sq);
    float mu   = s * (1.f / 256.f);
    float var  = sq * (1.f / 256.f) - mu * mu;
    float rstd = rsqrtf(var + 1e-5f);

    const float4* g4 = (const float4*)gamma;
    const float4* b4 = (const float4*)beta;
    float4 g0 = g4[lane], g1 = g4[32 + lane];
    float4 be0 = b4[lane], be1 = b4[32 + lane];

    row[lane] = make_float4((x0.x - mu) * rstd * g0.x + be0.x,
                            (x0.y - mu) * rstd * g0.y + be0.y,
                            (x0.z - mu) * rstd * g0.z + be0.z,
                            (x0.w - mu) * rstd * g0.w + be0.w);
    row[32 + lane] = make_float4((x1.x - mu) * rstd * g1.x + be1.x,
                                 (x1.y - mu) * rstd * g1.y + be1.y,
                                 (x1.z - mu) * rstd * g1.z + be1.z,
                                 (x1.w - mu) * rstd * g1.w + be1.w);
}

// ---------------- launch ---------------------------------------------------
extern "C" void kernel_launch(void* const* d_in, const int* in_sizes, int n_in,
                              void* d_out, int out_size) {
    const float* all_embs   = (const float*)d_in[0];
    const int*   center_idx = (const int*)d_in[1];
    const int*   nb_idx     = (const int*)d_in[2];
    const float* nb_w       = (const float*)d_in[3];
    const float* Wq         = (const float*)d_in[4];
    const float* Wk         = (const float*)d_in[5];
    const float* Wg         = (const float*)d_in[6];
    const float* bg         = (const float*)d_in[7];
    const float* Wo         = (const float*)d_in[8];
    const float* bo         = (const float*)d_in[9];
    const float* gamma      = (const float*)d_in[10];
    const float* beta       = (const float*)d_in[11];
    float* out = (float*)d_out;

    prep_kernel<<<1024, 256>>>(Wq, Wk, Wg, Wo);
    gemm_kernel<0><<<dim3(BATCH / 128, 6), 256>>>(all_embs, center_idx, bg, bo, nullptr);
    neigh_kernel<<<BATCH / 8, 256>>>(all_embs, nb_idx, nb_w);
    gemm_kernel<1><<<dim3(BATCH / 128, 2), 256>>>(all_embs, center_idx, bg, bo, out);
    ln_kernel<<<BATCH / 8, 256>>>(out, gamma, beta);
}

// round 2
// speedup vs baseline: 1.6508x; 1.6508x over previous
#include <cuda_runtime.h>
#include <cstdint>

#define BATCH   32768

// ---------------- device scratch (static, allocation-free) ----------------
__device__ __align__(128) float g_W1[768 * 256];          // rows 0-255: M^T, 256-511: Wg, 512-767: Wo1 (tf32-rounded)
__device__ __align__(128) float g_W2[256 * 256];          // Wo2 (tf32-rounded)
__device__ __align__(128) float g_E[(size_t)BATCH * 768]; // P | gate | E1
__device__ __align__(128) float g_ctx[(size_t)BATCH * 256];

__device__ __forceinline__ float rnd_tf32(float x) {
    uint32_t y;
    asm("cvt.rna.tf32.f32 %0, %1;" : "=r"(y) : "f"(x));
    return __uint_as_float(y);
}

__device__ __forceinline__ void cp_async16(void* smem_dst, const void* gmem_src) {
    uint32_t s = (uint32_t)__cvta_generic_to_shared(smem_dst);
    asm volatile("cp.async.cg.shared.global [%0], [%1], 16;\n" :: "r"(s), "l"(gmem_src));
}

__device__ __forceinline__ float warp_sum(float v) {
    v += __shfl_xor_sync(0xffffffffu, v, 16);
    v += __shfl_xor_sync(0xffffffffu, v, 8);
    v += __shfl_xor_sync(0xffffffffu, v, 4);
    v += __shfl_xor_sync(0xffffffffu, v, 2);
    v += __shfl_xor_sync(0xffffffffu, v, 1);
    return v;
}

// ---------------- K0: build fused weight matrices (tf32-rounded) ----------
__global__ void prep_kernel(const float* __restrict__ Wq, const float* __restrict__ Wk,
                            const float* __restrict__ Wg, const float* __restrict__ Wo) {
    int j = blockIdx.x;
    int e = threadIdx.x;
    if (j < 256) {
        float s = 0.f;
#pragma unroll 8
        for (int a = 0; a < 64; a++)
            s = fmaf(Wq[a * 256 + e], Wk[a * 256 + j], s);
        g_W1[j * 256 + e] = rnd_tf32(s);
    } else if (j < 512) {
        g_W1[j * 256 + e] = rnd_tf32(Wg[(j - 256) * 256 + e]);
    } else if (j < 768) {
        g_W1[j * 256 + e] = rnd_tf32(Wo[(j - 512) * 512 + e]);
    } else {
        g_W2[(j - 768) * 256 + e] = rnd_tf32(Wo[(j - 768) * 512 + 256 + e]);
    }
}

// ---------------- GEMM: tf32 mma, 128x128 tile, BK=32, cp.async 2-stage ---
// smem tiles are [row][k] with pitch 36 words (conflict-free for both the
// cp.async 16B stores and the (4*row+k)%32 fragment-load pattern).
#define PITCH 36
#define TILE_WORDS (128 * PITCH)

template <int EPI>
__global__ __launch_bounds__(256, 2)
void gemm_kernel(const float* __restrict__ all_embs,
                 const int* __restrict__ center_idx,
                 const float* __restrict__ bg,
                 const float* __restrict__ bo,
                 float* __restrict__ out) {
    extern __shared__ float sm[];               // [2 stages][A|B][128][PITCH]
    __shared__ int ridx[128];

    const int t    = threadIdx.x;
    const int lane = t & 31;
    const int warp = t >> 5;
    const int m0 = blockIdx.x * 128;
    const int n0 = blockIdx.y * 128;
    const float* Bmat = (EPI == 0) ? g_W1 : g_W2;

    if (t < 128) ridx[t] = center_idx[m0 + t];
    __syncthreads();

    float* As = sm;                              // stage s at As + s*TILE_WORDS
    float* Bs = sm + 2 * TILE_WORDS;

    const int lrow = t >> 1;                     // 0..127
    const int lch  = (t & 1) * 4;                // 0 or 4 (two 16B chunks each x2 iters)

    auto load_stage = [&](int kk, int s) {
        // A tile: 128 rows x 32 floats; 256 threads x 4 cp.async of 16B
#pragma unroll
        for (int i = 0; i < 4; i++) {
            int idx = t + i * 256;               // 0..1023
            int row = idx >> 3, ch = (idx & 7) * 4;
            const float* src = (EPI == 0)
                ? (all_embs + (size_t)ridx[row] * 256 + kk + ch)
                : (g_ctx + (size_t)(m0 + row) * 256 + kk + ch);
            cp_async16(&As[s * TILE_WORDS + row * PITCH + ch], src);
        }
#pragma unroll
        for (int i = 0; i < 4; i++) {
            int idx = t + i * 256;
            int row = idx >> 3, ch = (idx & 7) * 4;
            cp_async16(&Bs[s * TILE_WORDS + row * PITCH + ch],
                       Bmat + (size_t)(n0 + row) * 256 + kk + ch);
        }
        (void)lrow; (void)lch;
    };

    float acc[2][8][4] = {};

    const int g   = lane >> 2;
    const int tg  = lane & 3;
    const int mb  = (warp & 3) * 32;             // 4 warps along M
    const int nbo = (warp >> 2) * 64;            // 2 warps along N

    // prologue
    load_stage(0, 0);
    asm volatile("cp.async.commit_group;\n" ::: "memory");

#pragma unroll 1
    for (int it = 0; it < 8; ++it) {
        const int s = it & 1;
        if (it + 1 < 8) load_stage((it + 1) * 32, s ^ 1);
        asm volatile("cp.async.commit_group;\n" ::: "memory");
        asm volatile("cp.async.wait_group 1;\n" ::: "memory");
        __syncthreads();

        const float* A = As + s * TILE_WORDS;
        const float* B = Bs + s * TILE_WORDS;

#pragma unroll
        for (int ks = 0; ks < 4; ks++) {
            const int k0 = ks * 8;
            uint32_t a[2][4];
#pragma unroll
            for (int mt = 0; mt < 2; mt++) {
                int m = mb + mt * 16 + g;
                a[mt][0] = __float_as_uint(A[m * PITCH + k0 + tg]);
                a[mt][1] = __float_as_uint(A[(m + 8) * PITCH + k0 + tg]);
                a[mt][2] = __float_as_uint(A[m * PITCH + k0 + tg + 4]);
                a[mt][3] = __float_as_uint(A[(m + 8) * PITCH + k0 + tg + 4]);
            }
            uint32_t bf[8][2];
#pragma unroll
            for (int nt = 0; nt < 8; nt++) {
                int n = nbo + nt * 8 + g;
                bf[nt][0] = __float_as_uint(B[n * PITCH + k0 + tg]);
                bf[nt][1] = __float_as_uint(B[n * PITCH + k0 + tg + 4]);
            }
#pragma unroll
            for (int mt = 0; mt < 2; mt++)
#pragma unroll
                for (int nt = 0; nt < 8; nt++)
                    asm volatile(
                        "mma.sync.aligned.m16n8k8.row.col.f32.tf32.tf32.f32 "
                        "{%0,%1,%2,%3}, {%4,%5,%6,%7}, {%8,%9}, {%0,%1,%2,%3};\n"
                        : "+f"(acc[mt][nt][0]), "+f"(acc[mt][nt][1]),
                          "+f"(acc[mt][nt][2]), "+f"(acc[mt][nt][3])
                        : "r"(a[mt][0]), "r"(a[mt][1]), "r"(a[mt][2]), "r"(a[mt][3]),
                          "r"(bf[nt][0]), "r"(bf[nt][1]));
        }
        __syncthreads();
    }

    // epilogue
#pragma unroll
    for (int mt = 0; mt < 2; mt++) {
#pragma unroll
        for (int nt = 0; nt < 8; nt++) {
            int lc = nbo + nt * 8 + tg * 2;
#pragma unroll
            for (int h = 0; h < 2; h++) {
                int lr  = mb + mt * 16 + g + h * 8;
                int row = m0 + lr;
                float v0 = acc[mt][nt][h * 2 + 0];
                float v1 = acc[mt][nt][h * 2 + 1];
                int j = n0 + lc;
                if (EPI == 0) {
                    if (j < 256) {
                        // P: raw
                    } else if (j < 512) {
                        v0 = 1.f / (1.f + __expf(-(v0 + bg[j - 256])));
                        v1 = 1.f / (1.f + __expf(-(v1 + bg[j - 255])));
                    } else {
                        v0 += bo[j - 512];
                        v1 += bo[j - 511];
                    }
                    *(float2*)(g_E + (size_t)row * 768 + j) = make_float2(v0, v1);
                } else {
                    float2 e1 = *(const float2*)(g_E + (size_t)row * 768 + 512 + j);
                    const float* cen = all_embs + (size_t)ridx[lr] * 256;
                    float2 c2 = *(const float2*)(cen + j);
                    v0 += e1.x + c2.x;
                    v1 += e1.y + c2.y;
                    *(float2*)(out + (size_t)row * 256 + j) = make_float2(v0, v1);
                }
            }
        }
    }
}

// ---------------- K2: neighbor gather + logits + softmax + gated context --
__global__ __launch_bounds__(256, 1)
void neigh_kernel(const float* __restrict__ all_embs,
                  const int* __restrict__ nb_idx,
                  const float* __restrict__ nb_w) {
    const int warp = threadIdx.x >> 5;
    const int lane = threadIdx.x & 31;
    const int b = blockIdx.x * 8 + warp;

    int   myidx = 0;
    float mylw  = 0.f;
    if (lane < 16) {
        myidx = nb_idx[b * 16 + lane];
        mylw  = __logf(fmaxf(nb_w[b * 16 + lane], 1e-6f));
    }

    float4 nlo[16], nhi[16];
#pragma unroll
    for (int k = 0; k < 16; k++) {
        int r = __shfl_sync(0xffffffffu, myidx, k);
        const float4* rp = (const float4*)(all_embs + (size_t)r * 256);
        nlo[k] = rp[lane];
        nhi[k] = rp[32 + lane];
    }

    const float4* prow = (const float4*)(g_E + (size_t)b * 768);
    float4 plo = prow[lane], phi = prow[32 + lane];

    float logit[16];
#pragma unroll
    for (int k = 0; k < 16; k++) {
        float s = nlo[k].x * plo.x + nlo[k].y * plo.y + nlo[k].z * plo.z + nlo[k].w * plo.w
                + nhi[k].x * phi.x + nhi[k].y * phi.y + nhi[k].z * phi.z + nhi[k].w * phi.w;
        s = warp_sum(s);
        float lw = __shfl_sync(0xffffffffu, mylw, k);
        logit[k] = s * 0.125f + lw;   // SCALE = 64^-0.5
    }

    float mx = logit[0];
#pragma unroll
    for (int k = 1; k < 16; k++) mx = fmaxf(mx, logit[k]);
    float esum = 0.f;
#pragma unroll
    for (int k = 0; k < 16; k++) { logit[k] = __expf(logit[k] - mx); esum += logit[k]; }
    float inv = 1.f / esum;

    float4 clo = make_float4(0, 0, 0, 0), chi = make_float4(0, 0, 0, 0);
#pragma unroll
    for (int k = 0; k < 16; k++) {
        float a = logit[k] * inv;
        clo.x = fmaf(a, nlo[k].x, clo.x); clo.y = fmaf(a, nlo[k].y, clo.y);
        clo.z = fmaf(a, nlo[k].z, clo.z); clo.w = fmaf(a, nlo[k].w, clo.w);
        chi.x = fmaf(a, nhi[k].x, chi.x); chi.y = fmaf(a, nhi[k].y, chi.y);
        chi.z = fmaf(a, nhi[k].z, chi.z); chi.w = fmaf(a, nhi[k].w, chi.w);
    }

    const float4* grow = (const float4*)(g_E + (size_t)b * 768 + 256);
    float4 glo = grow[lane], ghi = grow[32 + lane];
    float4* crow = (float4*)(g_ctx + (size_t)b * 256);
    crow[lane]      = make_float4(glo.x * clo.x, glo.y * clo.y, glo.z * clo.z, glo.w * clo.w);
    crow[32 + lane] = make_float4(ghi.x * chi.x, ghi.y * chi.y, ghi.z * chi.z, ghi.w * chi.w);
}

// ---------------- K4: layernorm (in-place on d_out) ------------------------
__global__ void ln_kernel(float* __restrict__ out,
                          const float* __restrict__ gamma,
                          const float* __restrict__ beta) {
    const int warp = threadIdx.x >> 5;
    const int lane = threadIdx.x & 31;
    const int r = blockIdx.x * 8 + warp;
    float4* row = (float4*)(out + (size_t)r * 256);
    float4 x0 = row[lane], x1 = row[32 + lane];

    float s  = x0.x + x0.y + x0.z + x0.w + x1.x + x1.y + x1.z + x1.w;
    float sq = x0.x * x0.x + x0.y * x0.y + x0.z * x0.z + x0.w * x0.w
             + x1.x * x1.x + x1.y * x1.y + x1.z * x1.z + x1.w * x1.w;
    s  = warp_sum(s);
    sq = warp_sum(sq);
    float mu   = s * (1.f / 256.f);
    float var  = sq * (1.f / 256.f) - mu * mu;
    float rstd = rsqrtf(var + 1e-5f);

    const float4* g4 = (const float4*)gamma;
    const float4* b4 = (const float4*)beta;
    float4 g0 = g4[lane], g1 = g4[32 + lane];
    float4 be0 = b4[lane], be1 = b4[32 + lane];

    row[lane] = make_float4((x0.x - mu) * rstd * g0.x + be0.x,
                            (x0.y - mu) * rstd * g0.y + be0.y,
                            (x0.z - mu) * rstd * g0.z + be0.z,
                            (x0.w - mu) * rstd * g0.w + be0.w);
    row[32 + lane] = make_float4((x1.x - mu) * rstd * g1.x + be1.x,
                                 (x1.y - mu) * rstd * g1.y + be1.y,
                                 (x1.z - mu) * rstd * g1.z + be1.z,
                                 (x1.w - mu) * rstd * g1.w + be1.w);
}

// ---------------- launch ---------------------------------------------------
extern "C" void kernel_launch(void* const* d_in, const int* in_sizes, int n_in,
                              void* d_out, int out_size) {
    const float* all_embs   = (const float*)d_in[0];
    const int*   center_idx = (const int*)d_in[1];
    const int*   nb_idx     = (const int*)d_in[2];
    const float* nb_w       = (const float*)d_in[3];
    const float* Wq         = (const float*)d_in[4];
    const float* Wk         = (const float*)d_in[5];
    const float* Wg         = (const float*)d_in[6];
    const float* bg         = (const float*)d_in[7];
    const float* Wo         = (const float*)d_in[8];
    const float* bo         = (const float*)d_in[9];
    const float* gamma      = (const float*)d_in[10];
    const float* beta       = (const float*)d_in[11];
    float* out = (float*)d_out;

    const int smem_bytes = 4 * TILE_WORDS * sizeof(float);   // 73728
    static int configured = 0;
    if (!configured) {
        cudaFuncSetAttribute(gemm_kernel<0>, cudaFuncAttributeMaxDynamicSharedMemorySize, smem_bytes);
        cudaFuncSetAttribute(gemm_kernel<1>, cudaFuncAttributeMaxDynamicSharedMemorySize, smem_bytes);
        configured = 1;
    }

    prep_kernel<<<1024, 256>>>(Wq, Wk, Wg, Wo);
    gemm_kernel<0><<<dim3(BATCH / 128, 6), 256, smem_bytes>>>(all_embs, center_idx, bg, bo, nullptr);
    neigh_kernel<<<BATCH / 8, 256>>>(all_embs, nb_idx, nb_w);
    gemm_kernel<1><<<dim3(BATCH / 128, 2), 256, smem_bytes>>>(all_embs, center_idx, bg, bo, out);
    ln_kernel<<<BATCH / 8, 256>>>(out, gamma, beta);
}

// round 3
// speedup vs baseline: 1.6640x; 1.0080x over previous
#include <cuda_runtime.h>
#include <cstdint>

#define BATCH   32768
#define PITCH   36
#define A_WORDS (128 * PITCH)
#define B_WORDS (256 * PITCH)
#define STAGE_WORDS (A_WORDS + B_WORDS)

// ---------------- device scratch (static, allocation-free) ----------------
__device__ __align__(128) float g_W1[768 * 256];          // M^T | Wg | Wo1 (tf32-rounded)
__device__ __align__(128) float g_W2[256 * 256];          // Wo2 (tf32-rounded)
__device__ __align__(128) float g_E[(size_t)BATCH * 768]; // P | gate | E1
__device__ __align__(128) float g_ctx[(size_t)BATCH * 256];

__device__ __forceinline__ float rnd_tf32(float x) {
    uint32_t y;
    asm("cvt.rna.tf32.f32 %0, %1;" : "=r"(y) : "f"(x));
    return __uint_as_float(y);
}

__device__ __forceinline__ void cp_async16(void* smem_dst, const void* gmem_src) {
    uint32_t s = (uint32_t)__cvta_generic_to_shared(smem_dst);
    asm volatile("cp.async.cg.shared.global [%0], [%1], 16;\n" :: "r"(s), "l"(gmem_src));
}

__device__ __forceinline__ void ldsm_x4(uint32_t& r0, uint32_t& r1, uint32_t& r2, uint32_t& r3,
                                        uint32_t saddr) {
    asm volatile("ldmatrix.sync.aligned.m8n8.x4.shared.b16 {%0,%1,%2,%3}, [%4];"
                 : "=r"(r0), "=r"(r1), "=r"(r2), "=r"(r3) : "r"(saddr));
}

__device__ __forceinline__ float warp_sum(float v) {
    v += __shfl_xor_sync(0xffffffffu, v, 16);
    v += __shfl_xor_sync(0xffffffffu, v, 8);
    v += __shfl_xor_sync(0xffffffffu, v, 4);
    v += __shfl_xor_sync(0xffffffffu, v, 2);
    v += __shfl_xor_sync(0xffffffffu, v, 1);
    return v;
}

// ---------------- K0: build fused weight matrices (tf32-rounded) ----------
__global__ void prep_kernel(const float* __restrict__ Wq, const float* __restrict__ Wk,
                            const float* __restrict__ Wg, const float* __restrict__ Wo) {
    int j = blockIdx.x;
    int e = threadIdx.x;
    if (j < 256) {
        float s = 0.f;
#pragma unroll 8
        for (int a = 0; a < 64; a++)
            s = fmaf(Wq[a * 256 + e], Wk[a * 256 + j], s);
        g_W1[j * 256 + e] = rnd_tf32(s);
    } else if (j < 512) {
        g_W1[j * 256 + e] = rnd_tf32(Wg[(j - 256) * 256 + e]);
    } else if (j < 768) {
        g_W1[j * 256 + e] = rnd_tf32(Wo[(j - 512) * 512 + e]);
    } else {
        g_W2[(j - 768) * 256 + e] = rnd_tf32(Wo[(j - 768) * 512 + 256 + e]);
    }
}

// ---------------- GEMM: tf32 mma, 128x256 CTA tile, BK=32, ldmatrix frags --
// 512 threads = 16 warps (4 M-groups x 4 N-groups), warp tile 32x64.
// EPI==0: A = gathered centers, B = g_W1 (N=768), epilogue -> g_E (P/gate/E1)
// EPI==1: A = g_ctx, B = g_W2 (N=256), epilogue adds E1+center then fused LN -> out
template <int EPI>
__global__ __launch_bounds__(512, 1)
void gemm_kernel(const float* __restrict__ all_embs,
                 const int* __restrict__ center_idx,
                 const float* __restrict__ bg,
                 const float* __restrict__ bo,
                 const float* __restrict__ gamma,
                 const float* __restrict__ beta,
                 float* __restrict__ out) {
    extern __shared__ float sm[];             // [2 stages][A 128xPITCH | B 256xPITCH]
    __shared__ int   ridx[128];
    __shared__ float redS[128][4];
    __shared__ float redQ[128][4];

    const int t    = threadIdx.x;
    const int lane = t & 31;
    const int warp = t >> 5;
    const int m0 = blockIdx.x * 128;
    const int n0 = blockIdx.y * 256;
    const float* Bmat = (EPI == 0) ? g_W1 : g_W2;

    if (t < 128) ridx[t] = center_idx[m0 + t];
    __syncthreads();

    const uint32_t sm_u32 = (uint32_t)__cvta_generic_to_shared(sm);

    const int g   = lane >> 2;
    const int tg  = lane & 3;
    const int mb  = (warp & 3) * 32;          // M group (32 rows)
    const int nbo = (warp >> 2) * 64;         // N group (64 cols)

    // ldmatrix per-lane byte offsets within a stage
    uint32_t a_off[2], b_off[4];
#pragma unroll
    for (int mt = 0; mt < 2; mt++)
        a_off[mt] = ((mb + mt * 16 + (lane & 15)) * PITCH + ((lane >> 4) & 1) * 4) * 4;
#pragma unroll
    for (int p = 0; p < 4; p++)
        b_off[p] = (A_WORDS + (nbo + p * 16 + ((lane >> 4) & 1) * 8 + (lane & 7)) * PITCH
                    + ((lane >> 3) & 1) * 4) * 4;

    auto load_stage = [&](int kk, int s) {
        float* base = sm + s * STAGE_WORDS;
#pragma unroll
        for (int i = 0; i < 2; i++) {         // A: 128 rows x 8 chunks = 1024
            int idx = t + i * 512;
            int row = idx >> 3, ch = (idx & 7) * 4;
            const float* src = (EPI == 0)
                ? (all_embs + (size_t)ridx[row] * 256 + kk + ch)
                : (g_ctx + (size_t)(m0 + row) * 256 + kk + ch);
            cp_async16(base + row * PITCH + ch, src);
        }
#pragma unroll
        for (int i = 0; i < 4; i++) {         // B: 256 rows x 8 chunks = 2048
            int idx = t + i * 512;
            int row = idx >> 3, ch = (idx & 7) * 4;
            cp_async16(base + A_WORDS + row * PITCH + ch,
                       Bmat + (size_t)(n0 + row) * 256 + kk + ch);
        }
    };

    float acc[2][8][4] = {};

    load_stage(0, 0);
    asm volatile("cp.async.commit_group;\n" ::: "memory");

#pragma unroll 1
    for (int it = 0; it < 8; ++it) {
        const int s = it & 1;
        asm volatile("cp.async.wait_group 0;\n" ::: "memory");
        __syncthreads();
        if (it + 1 < 8) load_stage((it + 1) * 32, s ^ 1);
        asm volatile("cp.async.commit_group;\n" ::: "memory");

        const uint32_t stage = sm_u32 + s * (STAGE_WORDS * 4);
#pragma unroll
        for (int ks = 0; ks < 4; ks++) {
            const uint32_t kbyte = ks * 32;   // 8 floats
            uint32_t a[2][4];
#pragma unroll
            for (int mt = 0; mt < 2; mt++)
                ldsm_x4(a[mt][0], a[mt][1], a[mt][2], a[mt][3], stage + a_off[mt] + kbyte);
            uint32_t bf[8][2];
#pragma unroll
            for (int p = 0; p < 4; p++)
                ldsm_x4(bf[2 * p][0], bf[2 * p][1], bf[2 * p + 1][0], bf[2 * p + 1][1],
                        stage + b_off[p] + kbyte);
#pragma unroll
            for (int mt = 0; mt < 2; mt++)
#pragma unroll
                for (int nt = 0; nt < 8; nt++)
                    asm volatile(
                        "mma.sync.aligned.m16n8k8.row.col.f32.tf32.tf32.f32 "
                        "{%0,%1,%2,%3}, {%4,%5,%6,%7}, {%8,%9}, {%0,%1,%2,%3};\n"
                        : "+f"(acc[mt][nt][0]), "+f"(acc[mt][nt][1]),
                          "+f"(acc[mt][nt][2]), "+f"(acc[mt][nt][3])
                        : "r"(a[mt][0]), "r"(a[mt][1]), "r"(a[mt][2]), "r"(a[mt][3]),
                          "r"(bf[nt][0]), "r"(bf[nt][1]));
        }
        __syncthreads();
    }

    if (EPI == 0) {
#pragma unroll
        for (int mt = 0; mt < 2; mt++)
#pragma unroll
            for (int nt = 0; nt < 8; nt++) {
                int lc = nbo + nt * 8 + tg * 2;
#pragma unroll
                for (int h = 0; h < 2; h++) {
                    int row = m0 + mb + mt * 16 + g + h * 8;
                    float v0 = acc[mt][nt][h * 2 + 0];
                    float v1 = acc[mt][nt][h * 2 + 1];
                    int j = n0 + lc;
                    if (j < 256) {
                        // P: raw
                    } else if (j < 512) {
                        v0 = 1.f / (1.f + __expf(-(v0 + bg[j - 256])));
                        v1 = 1.f / (1.f + __expf(-(v1 + bg[j - 255])));
                    } else {
                        v0 += bo[j - 512];
                        v1 += bo[j - 511];
                    }
                    *(float2*)(g_E + (size_t)row * 768 + j) = make_float2(v0, v1);
                }
            }
    } else {
        // add E1 + center, accumulate row partial sums, fused LayerNorm
        float rs[4] = {0.f, 0.f, 0.f, 0.f};
        float rq[4] = {0.f, 0.f, 0.f, 0.f};
#pragma unroll
        for (int mt = 0; mt < 2; mt++)
#pragma unroll
            for (int h = 0; h < 2; h++) {
                int lr = mb + mt * 16 + g + h * 8;
                int row = m0 + lr;
                const float* cen = all_embs + (size_t)ridx[lr] * 256;
                const float* e1r = g_E + (size_t)row * 768 + 512;
                float s = 0.f, q = 0.f;
#pragma unroll
                for (int nt = 0; nt < 8; nt++) {
                    int j = nbo + nt * 8 + tg * 2;
                    float2 e1 = *(const float2*)(e1r + j);
                    float2 c2 = *(const float2*)(cen + j);
                    float v0 = acc[mt][nt][h * 2 + 0] + e1.x + c2.x;
                    float v1 = acc[mt][nt][h * 2 + 1] + e1.y + c2.y;
                    acc[mt][nt][h * 2 + 0] = v0;
                    acc[mt][nt][h * 2 + 1] = v1;
                    s += v0 + v1;
                    q += v0 * v0 + v1 * v1;
                }
                rs[mt * 2 + h] = s;
                rq[mt * 2 + h] = q;
            }
        // reduce over tg quad
#pragma unroll
        for (int i = 0; i < 4; i++) {
            rs[i] += __shfl_xor_sync(0xffffffffu, rs[i], 1);
            rs[i] += __shfl_xor_sync(0xffffffffu, rs[i], 2);
            rq[i] += __shfl_xor_sync(0xffffffffu, rq[i], 1);
            rq[i] += __shfl_xor_sync(0xffffffffu, rq[i], 2);
        }
        const int nw = warp >> 2;
        if (tg == 0) {
#pragma unroll
            for (int mt = 0; mt < 2; mt++)
#pragma unroll
                for (int h = 0; h < 2; h++) {
                    int lr = mb + mt * 16 + g + h * 8;
                    redS[lr][nw] = rs[mt * 2 + h];
                    redQ[lr][nw] = rq[mt * 2 + h];
                }
        }
        __syncthreads();
        float mu[4], rstd[4];
#pragma unroll
        for (int mt = 0; mt < 2; mt++)
#pragma unroll
            for (int h = 0; h < 2; h++) {
                int lr = mb + mt * 16 + g + h * 8;
                float s = redS[lr][0] + redS[lr][1] + redS[lr][2] + redS[lr][3];
                float q = redQ[lr][0] + redQ[lr][1] + redQ[lr][2] + redQ[lr][3];
                float m = s * (1.f / 256.f);
                float v = q * (1.f / 256.f) - m * m;
                mu[mt * 2 + h] = m;
                rstd[mt * 2 + h] = rsqrtf(v + 1e-5f);
            }
#pragma unroll
        for (int mt = 0; mt < 2; mt++)
#pragma unroll
            for (int nt = 0; nt < 8; nt++) {
                int j = nbo + nt * 8 + tg * 2;
                float2 gm = *(const float2*)(gamma + j);
                float2 bt = *(const float2*)(beta + j);
#pragma unroll
                for (int h = 0; h < 2; h++) {
                    int row = m0 + mb + mt * 16 + g + h * 8;
                    float m = mu[mt * 2 + h], r = rstd[mt * 2 + h];
                    float o0 = (acc[mt][nt][h * 2 + 0] - m) * r * gm.x + bt.x;
                    float o1 = (acc[mt][nt][h * 2 + 1] - m) * r * gm.y + bt.y;
                    *(float2*)(out + (size_t)row * 256 + j) = make_float2(o0, o1);
                }
            }
    }
}

// ---------------- K2: neighbor gather + logits + softmax + gated context --
__global__ __launch_bounds__(256, 1)
void neigh_kernel(const float* __restrict__ all_embs,
                  const int* __restrict__ nb_idx,
                  const float* __restrict__ nb_w) {
    const int warp = threadIdx.x >> 5;
    const int lane = threadIdx.x & 31;
    const int b = blockIdx.x * 8 + warp;

    int   myidx = 0;
    float mylw  = 0.f;
    if (lane < 16) {
        myidx = nb_idx[b * 16 + lane];
        mylw  = __logf(fmaxf(nb_w[b * 16 + lane], 1e-6f));
    }

    float4 nlo[16], nhi[16];
#pragma unroll
    for (int k = 0; k < 16; k++) {
        int r = __shfl_sync(0xffffffffu, myidx, k);
        const float4* rp = (const float4*)(all_embs + (size_t)r * 256);
        nlo[k] = rp[lane];
        nhi[k] = rp[32 + lane];
    }

    const float4* prow = (const float4*)(g_E + (size_t)b * 768);
    float4 plo = prow[lane], phi = prow[32 + lane];

    float logit[16];
#pragma unroll
    for (int k = 0; k < 16; k++) {
        float s = nlo[k].x * plo.x + nlo[k].y * plo.y + nlo[k].z * plo.z + nlo[k].w * plo.w
                + nhi[k].x * phi.x + nhi[k].y * phi.y + nhi[k].z * phi.z + nhi[k].w * phi.w;
        s = warp_sum(s);
        float lw = __shfl_sync(0xffffffffu, mylw, k);
        logit[k] = s * 0.125f + lw;   // SCALE = 64^-0.5
    }

    float mx = logit[0];
#pragma unroll
    for (int k = 1; k < 16; k++) mx = fmaxf(mx, logit[k]);
    float esum = 0.f;
#pragma unroll
    for (int k = 0; k < 16; k++) { logit[k] = __expf(logit[k] - mx); esum += logit[k]; }
    float inv = 1.f / esum;

    float4 clo = make_float4(0, 0, 0, 0), chi = make_float4(0, 0, 0, 0);
#pragma unroll
    for (int k = 0; k < 16; k++) {
        float a = logit[k] * inv;
        clo.x = fmaf(a, nlo[k].x, clo.x); clo.y = fmaf(a, nlo[k].y, clo.y);
        clo.z = fmaf(a, nlo[k].z, clo.z); clo.w = fmaf(a, nlo[k].w, clo.w);
        chi.x = fmaf(a, nhi[k].x, chi.x); chi.y = fmaf(a, nhi[k].y, chi.y);
        chi.z = fmaf(a, nhi[k].z, chi.z); chi.w = fmaf(a, nhi[k].w, chi.w);
    }

    const float4* grow = (const float4*)(g_E + (size_t)b * 768 + 256);
    float4 glo = grow[lane], ghi = grow[32 + lane];
    float4* crow = (float4*)(g_ctx + (size_t)b * 256);
    crow[lane]      = make_float4(glo.x * clo.x, glo.y * clo.y, glo.z * clo.z, glo.w * clo.w);
    crow[32 + lane] = make_float4(ghi.x * chi.x, ghi.y * chi.y, ghi.z * chi.z, ghi.w * chi.w);
}

// ---------------- launch ---------------------------------------------------
extern "C" void kernel_launch(void* const* d_in, const int* in_sizes, int n_in,
                              void* d_out, int out_size) {
    const float* all_embs   = (const float*)d_in[0];
    const int*   center_idx = (const int*)d_in[1];
    const int*   nb_idx     = (const int*)d_in[2];
    const float* nb_w       = (const float*)d_in[3];
    const float* Wq         = (const float*)d_in[4];
    const float* Wk         = (const float*)d_in[5];
    const float* Wg         = (const float*)d_in[6];
    const float* bg         = (const float*)d_in[7];
    const float* Wo         = (const float*)d_in[8];
    const float* bo         = (const float*)d_in[9];
    const float* gamma      = (const float*)d_in[10];
    const float* beta       = (const float*)d_in[11];
    float* out = (float*)d_out;

    const int smem_bytes = 2 * STAGE_WORDS * sizeof(float);   // 110592
    static int configured = 0;
    if (!configured) {
        cudaFuncSetAttribute(gemm_kernel<0>, cudaFuncAttributeMaxDynamicSharedMemorySize, smem_bytes);
        cudaFuncSetAttribute(gemm_kernel<1>, cudaFuncAttributeMaxDynamicSharedMemorySize, smem_bytes);
        configured = 1;
    }

    prep_kernel<<<1024, 256>>>(Wq, Wk, Wg, Wo);
    gemm_kernel<0><<<dim3(BATCH / 128, 3), 512, smem_bytes>>>(all_embs, center_idx, bg, bo, gamma, beta, nullptr);
    neigh_kernel<<<BATCH / 8, 256>>>(all_embs, nb_idx, nb_w);
    gemm_kernel<1><<<dim3(BATCH / 128, 1), 512, smem_bytes>>>(all_embs, center_idx, bg, bo, gamma, beta, out);
}